// round 1
// baseline (speedup 1.0000x reference)
#include <cuda_runtime.h>

#define B 8
#define S 1024
#define DIM 768
#define H 8
#define NEGV -1e10f
#define RS96 0.1020620726159658f  // 1/sqrt(96)

// Scratch (static device globals — allocation-free per harness rules)
__device__ float g_Q[B * S * DIM];
__device__ float g_K[B * S * DIM];
__device__ float g_logit[B * S];
__device__ float g_aw[B * S];
__device__ float g_R[B * S * H];
__device__ float g_T[B * H * DIM];

// ---------------------------------------------------------------------------
// K0: zero the R accumulator (filled via atomics each launch)
// ---------------------------------------------------------------------------
__global__ void k0_zeroR() {
    int i = blockIdx.x * blockDim.x + threadIdx.x;
    if (i < B * S * H) g_R[i] = 0.f;
}

// ---------------------------------------------------------------------------
// K1a: span logits  l[b,s] = X[b,s,:] . w  (masked with NEG where tag==0)
// warp per row, 8 warps/block
// ---------------------------------------------------------------------------
__global__ void k1a_logits(const float* __restrict__ X,
                           const int* __restrict__ tags,
                           const float* __restrict__ w) {
    int warp = threadIdx.x >> 5, lane = threadIdx.x & 31;
    int row = blockIdx.x * 8 + warp;
    const float4* xr = (const float4*)(X + (size_t)row * DIM);
    const float4* wr = (const float4*)w;
    float s = 0.f;
#pragma unroll
    for (int i = 0; i < 6; i++) {
        float4 a = xr[lane + 32 * i];
        float4 b = wr[lane + 32 * i];
        s += a.x * b.x + a.y * b.y + a.z * b.z + a.w * b.w;
    }
#pragma unroll
    for (int o = 16; o; o >>= 1) s += __shfl_xor_sync(0xffffffffu, s, o);
    if (lane == 0) g_logit[row] = (tags[row] == 0) ? NEGV : s;
}

// ---------------------------------------------------------------------------
// K1b: softmax over seq per batch -> aw[b,s].  exp(NEG - max) underflows to
// exactly 0, matching the reference's padded-query behavior.
// ---------------------------------------------------------------------------
__global__ void k1b_softmax() {
    __shared__ float red[256];
    int b = blockIdx.x, t = threadIdx.x;
    float l[4];
#pragma unroll
    for (int i = 0; i < 4; i++) l[i] = g_logit[b * S + t + 256 * i];
    float mx = fmaxf(fmaxf(l[0], l[1]), fmaxf(l[2], l[3]));
    red[t] = mx;
    __syncthreads();
    for (int o = 128; o; o >>= 1) {
        if (t < o) red[t] = fmaxf(red[t], red[t + o]);
        __syncthreads();
    }
    mx = red[0];
    __syncthreads();
    float e[4], sum = 0.f;
#pragma unroll
    for (int i = 0; i < 4; i++) { e[i] = __expf(l[i] - mx); sum += e[i]; }
    red[t] = sum;
    __syncthreads();
    for (int o = 128; o; o >>= 1) {
        if (t < o) red[t] += red[t + o];
        __syncthreads();
    }
    float inv = 1.f / red[0];
#pragma unroll
    for (int i = 0; i < 4; i++) g_aw[b * S + t + 256 * i] = e[i] * inv;
}

// ---------------------------------------------------------------------------
// K2: dual projection GEMM  Q = (X Wq^T)*RS96,  K = X Wk^T
// 64x64 tile, Tk=16, 256 threads, 4x4 micro per output, X tile shared.
// ---------------------------------------------------------------------------
__global__ void __launch_bounds__(256) k2_proj(const float* __restrict__ X,
                                               const float* __restrict__ Wq,
                                               const float* __restrict__ Wk) {
    __shared__ float Xs[16][68];
    __shared__ float Aq[16][68];
    __shared__ float Ak[16][68];
    int i0 = blockIdx.x * 64, j0 = blockIdx.y * 64;
    int t = threadIdx.x, tx = t & 15, ty = t >> 4;
    int lr = t >> 2, lc = (t & 3) << 2;
    float accq[4][4], acck[4][4];
#pragma unroll
    for (int a = 0; a < 4; a++)
#pragma unroll
        for (int c = 0; c < 4; c++) { accq[a][c] = 0.f; acck[a][c] = 0.f; }

    for (int m0 = 0; m0 < DIM; m0 += 16) {
        float4 vx = *(const float4*)(X + (size_t)(i0 + lr) * DIM + m0 + lc);
        float4 vq = *(const float4*)(Wq + (size_t)(j0 + lr) * DIM + m0 + lc);
        float4 vk = *(const float4*)(Wk + (size_t)(j0 + lr) * DIM + m0 + lc);
        __syncthreads();
        Xs[lc + 0][lr] = vx.x; Xs[lc + 1][lr] = vx.y; Xs[lc + 2][lr] = vx.z; Xs[lc + 3][lr] = vx.w;
        Aq[lc + 0][lr] = vq.x; Aq[lc + 1][lr] = vq.y; Aq[lc + 2][lr] = vq.z; Aq[lc + 3][lr] = vq.w;
        Ak[lc + 0][lr] = vk.x; Ak[lc + 1][lr] = vk.y; Ak[lc + 2][lr] = vk.z; Ak[lc + 3][lr] = vk.w;
        __syncthreads();
#pragma unroll
        for (int mk = 0; mk < 16; mk++) {
            float4 a4 = *(float4*)&Xs[mk][ty << 2];
            float4 q4 = *(float4*)&Aq[mk][tx << 2];
            float4 k4 = *(float4*)&Ak[mk][tx << 2];
            float av[4] = {a4.x, a4.y, a4.z, a4.w};
            float qv[4] = {q4.x, q4.y, q4.z, q4.w};
            float kv[4] = {k4.x, k4.y, k4.z, k4.w};
#pragma unroll
            for (int qi = 0; qi < 4; qi++)
#pragma unroll
                for (int ki = 0; ki < 4; ki++) {
                    accq[qi][ki] += av[qi] * qv[ki];
                    acck[qi][ki] += av[qi] * kv[ki];
                }
        }
    }
#pragma unroll
    for (int qi = 0; qi < 4; qi++) {
        size_t o = (size_t)(i0 + (ty << 2) + qi) * DIM + j0 + (tx << 2);
        float4 q4 = make_float4(accq[qi][0] * RS96, accq[qi][1] * RS96,
                                accq[qi][2] * RS96, accq[qi][3] * RS96);
        float4 k4 = make_float4(acck[qi][0], acck[qi][1], acck[qi][2], acck[qi][3]);
        *(float4*)(g_Q + o) = q4;
        *(float4*)(g_K + o) = k4;
    }
}

// ---------------------------------------------------------------------------
// K3: fused grouped QK^T + heads-softmax + aw-weighted reduction over q.
// Block = (b, qtile64, ktile64). 256 threads, 4x4 pairs/thread, 8 head accs
// each (heads interleave along m: acc[m&7] += Q[q,m]*K[k,m]).
// Result accumulated into R[b,k,h] via smem + global atomics.
// ---------------------------------------------------------------------------
__global__ void __launch_bounds__(256) k3_attn() {
    __shared__ float Qs[16][68];
    __shared__ float Ks[16][68];
    __shared__ float Rs[64][8];
    int b = blockIdx.z;
    int q0 = blockIdx.y * 64, k0 = blockIdx.x * 64;
    int t = threadIdx.x, tx = t & 15, ty = t >> 4;
    int lr = t >> 2, lc = (t & 3) << 2;
    for (int i = t; i < 512; i += 256) ((float*)Rs)[i] = 0.f;
    const float* Qb = g_Q + (size_t)(b * S + q0) * DIM;
    const float* Kb = g_K + (size_t)(b * S + k0) * DIM;
    float acc[4][4][8];
#pragma unroll
    for (int qi = 0; qi < 4; qi++)
#pragma unroll
        for (int ki = 0; ki < 4; ki++)
#pragma unroll
            for (int h = 0; h < 8; h++) acc[qi][ki][h] = 0.f;

    for (int m0 = 0; m0 < DIM; m0 += 16) {
        float4 vq = *(const float4*)(Qb + (size_t)lr * DIM + m0 + lc);
        float4 vk = *(const float4*)(Kb + (size_t)lr * DIM + m0 + lc);
        __syncthreads();
        Qs[lc + 0][lr] = vq.x; Qs[lc + 1][lr] = vq.y; Qs[lc + 2][lr] = vq.z; Qs[lc + 3][lr] = vq.w;
        Ks[lc + 0][lr] = vk.x; Ks[lc + 1][lr] = vk.y; Ks[lc + 2][lr] = vk.z; Ks[lc + 3][lr] = vk.w;
        __syncthreads();
#pragma unroll
        for (int mk = 0; mk < 16; mk++) {
            float4 a4 = *(float4*)&Qs[mk][ty << 2];
            float4 c4 = *(float4*)&Ks[mk][tx << 2];
            float av[4] = {a4.x, a4.y, a4.z, a4.w};
            float bv[4] = {c4.x, c4.y, c4.z, c4.w};
#pragma unroll
            for (int qi = 0; qi < 4; qi++)
#pragma unroll
                for (int ki = 0; ki < 4; ki++)
                    acc[qi][ki][mk & 7] += av[qi] * bv[ki];
        }
    }

    // epilogue: per-pair softmax over heads, weight by aw_q, reduce over q
    float val[4][8];
#pragma unroll
    for (int ki = 0; ki < 4; ki++)
#pragma unroll
        for (int h = 0; h < 8; h++) val[ki][h] = 0.f;

#pragma unroll
    for (int qi = 0; qi < 4; qi++) {
        float aw = g_aw[b * S + q0 + (ty << 2) + qi];
        if (aw != 0.f) {
#pragma unroll
            for (int ki = 0; ki < 4; ki++) {
                float mx = acc[qi][ki][0];
#pragma unroll
                for (int h = 1; h < 8; h++) mx = fmaxf(mx, acc[qi][ki][h]);
                float e[8], sum = 0.f;
#pragma unroll
                for (int h = 0; h < 8; h++) { e[h] = __expf(acc[qi][ki][h] - mx); sum += e[h]; }
                float w = aw / sum;
#pragma unroll
                for (int h = 0; h < 8; h++) val[ki][h] += w * e[h];
            }
        }
    }
#pragma unroll
    for (int ki = 0; ki < 4; ki++)
#pragma unroll
        for (int h = 0; h < 8; h++) atomicAdd(&Rs[(tx << 2) + ki][h], val[ki][h]);
    __syncthreads();
    for (int i = t; i < 512; i += 256) {
        int kk = i >> 3, h = i & 7;
        atomicAdd(&g_R[((size_t)b * S + k0 + kk) * H + h], Rs[kk][h]);
    }
}

// ---------------------------------------------------------------------------
// K4: T[b,h,m] = sum_k R[b,k,h] * X[b,k,m]   (replaces V projection!)
// ---------------------------------------------------------------------------
__global__ void __launch_bounds__(256) k4_T(const float* __restrict__ X) {
    __shared__ float Xs[64][64];
    __shared__ float Rs[64][8];
    int b = blockIdx.y;
    int m0 = blockIdx.x * 64;
    int t = threadIdx.x;
    int m = t & 63, hh = t >> 6;  // hh in 0..3, handles heads hh and hh+4
    float acc0 = 0.f, acc1 = 0.f;
    for (int kc = 0; kc < S; kc += 64) {
#pragma unroll
        for (int u = 0; u < 4; u++) {
            int lin = t + 256 * u;
            int r = lin >> 4, c = (lin & 15) << 2;
            *(float4*)&Xs[r][c] =
                *(const float4*)(X + (size_t)(b * S + kc + r) * DIM + m0 + c);
        }
        {
            float2 v = *(const float2*)(g_R + ((size_t)b * S + kc) * H + t * 2);
            *(float2*)&((float*)Rs)[t * 2] = v;
        }
        __syncthreads();
#pragma unroll 8
        for (int k = 0; k < 64; k++) {
            float x = Xs[k][m];
            acc0 += Rs[k][hh] * x;
            acc1 += Rs[k][hh + 4] * x;
        }
        __syncthreads();
    }
    g_T[((size_t)b * H + hh) * DIM + m0 + m] = acc0;
    g_T[((size_t)b * H + hh + 4) * DIM + m0 + m] = acc1;
}

// ---------------------------------------------------------------------------
// K5: out[b,j] = sum_m Wv[j,m] * T[b, j&7, m]   (warp per output)
// ---------------------------------------------------------------------------
__global__ void k5_out(const float* __restrict__ Wv, float* __restrict__ out) {
    int warp = threadIdx.x >> 5, lane = threadIdx.x & 31;
    int g = blockIdx.x * 8 + warp;  // 0..6143
    int b = g / DIM, j = g % DIM;
    int h = j & 7;
    const float4* wr = (const float4*)(Wv + (size_t)j * DIM);
    const float4* tr = (const float4*)(g_T + ((size_t)b * H + h) * DIM);
    float s = 0.f;
#pragma unroll
    for (int i = 0; i < 6; i++) {
        float4 a = wr[lane + 32 * i];
        float4 c = tr[lane + 32 * i];
        s += a.x * c.x + a.y * c.y + a.z * c.z + a.w * c.w;
    }
#pragma unroll
    for (int o = 16; o; o >>= 1) s += __shfl_xor_sync(0xffffffffu, s, o);
    if (lane == 0) out[(size_t)b * DIM + j] = s;
}

// ---------------------------------------------------------------------------
extern "C" void kernel_launch(void* const* d_in, const int* in_sizes, int n_in,
                              void* d_out, int out_size) {
    const float* X    = (const float*)d_in[0];
    const int*   tags = (const int*)d_in[1];
    const float* w    = (const float*)d_in[2];
    const float* Wq   = (const float*)d_in[3];
    const float* Wk   = (const float*)d_in[4];
    const float* Wv   = (const float*)d_in[5];
    float* out = (float*)d_out;

    k0_zeroR<<<(B * S * H + 255) / 256, 256>>>();
    k1a_logits<<<B * S / 8, 256>>>(X, tags, w);
    k1b_softmax<<<B, 256>>>();
    k2_proj<<<dim3(128, 12), 256>>>(X, Wq, Wk);
    k3_attn<<<dim3(16, 16, 8), 256>>>();
    k4_T<<<dim3(12, 8), 256>>>(X);
    k5_out<<<768, 256>>>(Wv, out);
}

// round 2
// speedup vs baseline: 1.5527x; 1.5527x over previous
#include <cuda_runtime.h>

#define B 8
#define S 1024
#define DIM 768
#define H 8
#define NEGV -1e10f
#define RS96 0.1020620726159658f  // 1/sqrt(96)
#define NI (B * S)                // 8192 total rows

// Scratch (static device globals — allocation-free per harness rules)
__device__ float g_Qt[DIM * NI];  // transposed: [m][i], i = b*S+s
__device__ float g_Kt[DIM * NI];
__device__ float g_logit[NI];
__device__ float g_aw[NI];
__device__ float g_R[NI * H];
__device__ float g_T[B * H * DIM];

// ---------------------------------------------------------------------------
__global__ void k0_zeroR() {
    int i = blockIdx.x * blockDim.x + threadIdx.x;
    if (i < NI * H) g_R[i] = 0.f;
}

// ---------------------------------------------------------------------------
// K1a: span logits  l[i] = X[i,:] . w  (masked with NEG where tag==0)
// ---------------------------------------------------------------------------
__global__ void k1a_logits(const float* __restrict__ X,
                           const int* __restrict__ tags,
                           const float* __restrict__ w) {
    int warp = threadIdx.x >> 5, lane = threadIdx.x & 31;
    int row = blockIdx.x * 8 + warp;
    const float4* xr = (const float4*)(X + (size_t)row * DIM);
    const float4* wr = (const float4*)w;
    float s = 0.f;
#pragma unroll
    for (int i = 0; i < 6; i++) {
        float4 a = xr[lane + 32 * i];
        float4 b = wr[lane + 32 * i];
        s += a.x * b.x + a.y * b.y + a.z * b.z + a.w * b.w;
    }
#pragma unroll
    for (int o = 16; o; o >>= 1) s += __shfl_xor_sync(0xffffffffu, s, o);
    if (lane == 0) g_logit[row] = (tags[row] == 0) ? NEGV : s;
}

// ---------------------------------------------------------------------------
// K1b: softmax over seq per batch -> aw[b,s]. exp(NEG-max) underflows to 0.
// ---------------------------------------------------------------------------
__global__ void k1b_softmax() {
    __shared__ float red[256];
    int b = blockIdx.x, t = threadIdx.x;
    float l[4];
#pragma unroll
    for (int i = 0; i < 4; i++) l[i] = g_logit[b * S + t + 256 * i];
    float mx = fmaxf(fmaxf(l[0], l[1]), fmaxf(l[2], l[3]));
    red[t] = mx;
    __syncthreads();
    for (int o = 128; o; o >>= 1) {
        if (t < o) red[t] = fmaxf(red[t], red[t + o]);
        __syncthreads();
    }
    mx = red[0];
    __syncthreads();
    float e[4], sum = 0.f;
#pragma unroll
    for (int i = 0; i < 4; i++) { e[i] = __expf(l[i] - mx); sum += e[i]; }
    red[t] = sum;
    __syncthreads();
    for (int o = 128; o; o >>= 1) {
        if (t < o) red[t] += red[t + o];
        __syncthreads();
    }
    float inv = 1.f / red[0];
#pragma unroll
    for (int i = 0; i < 4; i++) g_aw[b * S + t + 256 * i] = e[i] * inv;
}

// ---------------------------------------------------------------------------
// K2: dual projection GEMM, transposed outputs.
//   Qt[j][i] = RS96 * sum_m X[i][m] Wq[j][m];  Kt[j][i] = sum_m X[i][m] Wk[j][m]
// 128(i) x 64(j) tile, Tk=16, 256 threads, 8x4 micro per matrix (1 B/FMA).
// ---------------------------------------------------------------------------
__global__ void __launch_bounds__(256, 2) k2_proj(const float* __restrict__ X,
                                                  const float* __restrict__ Wq,
                                                  const float* __restrict__ Wk) {
    __shared__ float Xs[16][132];
    __shared__ float Aq[16][68];
    __shared__ float Ak[16][68];
    int i0 = blockIdx.x * 128, j0 = blockIdx.y * 64;
    int t = threadIdx.x, tx = t & 15, ty = t >> 4;
    int lr = t >> 2, lc = (t & 3) << 2;  // lr 0..63, lc {0,4,8,12}
    float accq[8][4], acck[8][4];
#pragma unroll
    for (int a = 0; a < 8; a++)
#pragma unroll
        for (int c = 0; c < 4; c++) { accq[a][c] = 0.f; acck[a][c] = 0.f; }

    for (int m0 = 0; m0 < DIM; m0 += 16) {
        float4 vx0 = *(const float4*)(X + (size_t)(i0 + lr) * DIM + m0 + lc);
        float4 vx1 = *(const float4*)(X + (size_t)(i0 + lr + 64) * DIM + m0 + lc);
        float4 vq  = *(const float4*)(Wq + (size_t)(j0 + lr) * DIM + m0 + lc);
        float4 vk  = *(const float4*)(Wk + (size_t)(j0 + lr) * DIM + m0 + lc);
        __syncthreads();
        Xs[lc + 0][lr] = vx0.x; Xs[lc + 1][lr] = vx0.y; Xs[lc + 2][lr] = vx0.z; Xs[lc + 3][lr] = vx0.w;
        Xs[lc + 0][lr + 64] = vx1.x; Xs[lc + 1][lr + 64] = vx1.y; Xs[lc + 2][lr + 64] = vx1.z; Xs[lc + 3][lr + 64] = vx1.w;
        Aq[lc + 0][lr] = vq.x; Aq[lc + 1][lr] = vq.y; Aq[lc + 2][lr] = vq.z; Aq[lc + 3][lr] = vq.w;
        Ak[lc + 0][lr] = vk.x; Ak[lc + 1][lr] = vk.y; Ak[lc + 2][lr] = vk.z; Ak[lc + 3][lr] = vk.w;
        __syncthreads();
#pragma unroll
        for (int mk = 0; mk < 16; mk++) {
            float4 a0 = *(float4*)&Xs[mk][ty * 8];
            float4 a1 = *(float4*)&Xs[mk][ty * 8 + 4];
            float4 q4 = *(float4*)&Aq[mk][tx * 4];
            float4 k4 = *(float4*)&Ak[mk][tx * 4];
            float av[8] = {a0.x, a0.y, a0.z, a0.w, a1.x, a1.y, a1.z, a1.w};
            float qv[4] = {q4.x, q4.y, q4.z, q4.w};
            float kv[4] = {k4.x, k4.y, k4.z, k4.w};
#pragma unroll
            for (int ii = 0; ii < 8; ii++)
#pragma unroll
                for (int jj = 0; jj < 4; jj++) {
                    accq[ii][jj] += av[ii] * qv[jj];
                    acck[ii][jj] += av[ii] * kv[jj];
                }
        }
    }
    // transposed write: rows j, contiguous along i
#pragma unroll
    for (int jj = 0; jj < 4; jj++) {
        size_t o = (size_t)(j0 + tx * 4 + jj) * NI + i0 + ty * 8;
        float4 q0 = make_float4(accq[0][jj] * RS96, accq[1][jj] * RS96,
                                accq[2][jj] * RS96, accq[3][jj] * RS96);
        float4 q1 = make_float4(accq[4][jj] * RS96, accq[5][jj] * RS96,
                                accq[6][jj] * RS96, accq[7][jj] * RS96);
        float4 k0v = make_float4(acck[0][jj], acck[1][jj], acck[2][jj], acck[3][jj]);
        float4 k1v = make_float4(acck[4][jj], acck[5][jj], acck[6][jj], acck[7][jj]);
        *(float4*)(g_Qt + o) = q0;
        *(float4*)(g_Qt + o + 4) = q1;
        *(float4*)(g_Kt + o) = k0v;
        *(float4*)(g_Kt + o + 4) = k1v;
    }
}

// ---------------------------------------------------------------------------
// K3: grouped QK^T + heads-softmax + aw-weighted q-reduction.
// 512 threads: t = (pair-group g)*8 + head h. Thread owns 8q x 8k pairs for
// ONE head (m ≡ h mod 8) -> 64 accs, 1 B/FMA from smem.
// Softmax over heads = bfly shuffles across the 8 lanes of the octet.
// ---------------------------------------------------------------------------
__global__ void __launch_bounds__(512, 1) k3_attn() {
    __shared__ float Qs[64][68];
    __shared__ float Ks[64][68];
    __shared__ float Rs[64][8];
    int b = blockIdx.z;
    int q0 = blockIdx.y * 64, k0 = blockIdx.x * 64;
    int t = threadIdx.x;
    int h = t & 7, g = t >> 3, gx = g & 7, gy = g >> 3;
    int iq = b * S + q0, ik = b * S + k0;
    int lr = t >> 4, lc = (t & 15) << 2;  // loader: rows lr, lr+32; cols lc..lc+3
    ((float*)Rs)[t] = 0.f;

    float acc[8][8];
#pragma unroll
    for (int a = 0; a < 8; a++)
#pragma unroll
        for (int c = 0; c < 8; c++) acc[a][c] = 0.f;

    for (int mc = 0; mc < DIM; mc += 64) {
        float4 a0 = *(const float4*)(g_Qt + (size_t)(mc + lr) * NI + iq + lc);
        float4 a1 = *(const float4*)(g_Qt + (size_t)(mc + lr + 32) * NI + iq + lc);
        float4 c0 = *(const float4*)(g_Kt + (size_t)(mc + lr) * NI + ik + lc);
        float4 c1 = *(const float4*)(g_Kt + (size_t)(mc + lr + 32) * NI + ik + lc);
        __syncthreads();
        *(float4*)&Qs[lr][lc] = a0;
        *(float4*)&Qs[lr + 32][lc] = a1;
        *(float4*)&Ks[lr][lc] = c0;
        *(float4*)&Ks[lr + 32][lc] = c1;
        __syncthreads();
#pragma unroll
        for (int u = 0; u < 8; u++) {
            int r = u * 8 + h;
            float4 qa = *(float4*)&Qs[r][gy * 8];
            float4 qb = *(float4*)&Qs[r][gy * 8 + 4];
            float4 ka = *(float4*)&Ks[r][gx * 8];
            float4 kb = *(float4*)&Ks[r][gx * 8 + 4];
            float qv[8] = {qa.x, qa.y, qa.z, qa.w, qb.x, qb.y, qb.z, qb.w};
            float kv[8] = {ka.x, ka.y, ka.z, ka.w, kb.x, kb.y, kb.z, kb.w};
#pragma unroll
            for (int qi = 0; qi < 8; qi++)
#pragma unroll
                for (int ki = 0; ki < 8; ki++)
                    acc[qi][ki] += qv[qi] * kv[ki];
        }
    }

    // epilogue: per-pair softmax over the 8 heads (8 lanes of this octet)
    unsigned mask = 0xFFu << ((t & 31) & 24);
    float rk[8];
#pragma unroll
    for (int ki = 0; ki < 8; ki++) rk[ki] = 0.f;
#pragma unroll
    for (int qi = 0; qi < 8; qi++) {
        float aw = g_aw[iq + gy * 8 + qi];  // uniform across octet
        if (aw != 0.f) {
#pragma unroll
            for (int ki = 0; ki < 8; ki++) {
                float v = acc[qi][ki];
                float mx = v;
                mx = fmaxf(mx, __shfl_xor_sync(mask, mx, 1));
                mx = fmaxf(mx, __shfl_xor_sync(mask, mx, 2));
                mx = fmaxf(mx, __shfl_xor_sync(mask, mx, 4));
                float e = __expf(v - mx);
                float s = e;
                s += __shfl_xor_sync(mask, s, 1);
                s += __shfl_xor_sync(mask, s, 2);
                s += __shfl_xor_sync(mask, s, 4);
                rk[ki] += aw * __fdividef(e, s);
            }
        }
    }
#pragma unroll
    for (int ki = 0; ki < 8; ki++) atomicAdd(&Rs[gx * 8 + ki][h], rk[ki]);
    __syncthreads();
    atomicAdd(&g_R[(size_t)(ik + (t >> 3)) * H + (t & 7)], Rs[t >> 3][t & 7]);
}

// ---------------------------------------------------------------------------
// K4: T[b,h,m] = sum_k R[b,k,h] * X[b,k,m]   (replaces V projection)
// ---------------------------------------------------------------------------
__global__ void __launch_bounds__(256) k4_T(const float* __restrict__ X) {
    __shared__ float Xs[64][64];
    __shared__ float Rs[64][8];
    int b = blockIdx.y;
    int m0 = blockIdx.x * 64;
    int t = threadIdx.x;
    int m = t & 63, hh = t >> 6;
    float acc0 = 0.f, acc1 = 0.f;
    for (int kc = 0; kc < S; kc += 64) {
#pragma unroll
        for (int u = 0; u < 4; u++) {
            int lin = t + 256 * u;
            int r = lin >> 4, c = (lin & 15) << 2;
            *(float4*)&Xs[r][c] =
                *(const float4*)(X + (size_t)(b * S + kc + r) * DIM + m0 + c);
        }
        {
            float2 v = *(const float2*)(g_R + ((size_t)b * S + kc) * H + t * 2);
            *(float2*)&((float*)Rs)[t * 2] = v;
        }
        __syncthreads();
#pragma unroll 8
        for (int k = 0; k < 64; k++) {
            float x = Xs[k][m];
            acc0 += Rs[k][hh] * x;
            acc1 += Rs[k][hh + 4] * x;
        }
        __syncthreads();
    }
    g_T[((size_t)b * H + hh) * DIM + m0 + m] = acc0;
    g_T[((size_t)b * H + hh + 4) * DIM + m0 + m] = acc1;
}

// ---------------------------------------------------------------------------
// K5: out[b,j] = sum_m Wv[j,m] * T[b, j&7, m]
// ---------------------------------------------------------------------------
__global__ void k5_out(const float* __restrict__ Wv, float* __restrict__ out) {
    int warp = threadIdx.x >> 5, lane = threadIdx.x & 31;
    int g = blockIdx.x * 8 + warp;
    int b = g / DIM, j = g % DIM;
    int h = j & 7;
    const float4* wr = (const float4*)(Wv + (size_t)j * DIM);
    const float4* tr = (const float4*)(g_T + ((size_t)b * H + h) * DIM);
    float s = 0.f;
#pragma unroll
    for (int i = 0; i < 6; i++) {
        float4 a = wr[lane + 32 * i];
        float4 c = tr[lane + 32 * i];
        s += a.x * c.x + a.y * c.y + a.z * c.z + a.w * c.w;
    }
#pragma unroll
    for (int o = 16; o; o >>= 1) s += __shfl_xor_sync(0xffffffffu, s, o);
    if (lane == 0) out[(size_t)b * DIM + j] = s;
}

// ---------------------------------------------------------------------------
extern "C" void kernel_launch(void* const* d_in, const int* in_sizes, int n_in,
                              void* d_out, int out_size) {
    const float* X    = (const float*)d_in[0];
    const int*   tags = (const int*)d_in[1];
    const float* w    = (const float*)d_in[2];
    const float* Wq   = (const float*)d_in[3];
    const float* Wk   = (const float*)d_in[4];
    const float* Wv   = (const float*)d_in[5];
    float* out = (float*)d_out;

    k0_zeroR<<<(NI * H + 255) / 256, 256>>>();
    k1a_logits<<<NI / 8, 256>>>(X, tags, w);
    k1b_softmax<<<B, 256>>>();
    k2_proj<<<dim3(64, 12), 256>>>(X, Wq, Wk);
    k3_attn<<<dim3(16, 16, 8), 512>>>();
    k4_T<<<dim3(12, 8), 256>>>(X);
    k5_out<<<768, 256>>>(Wv, out);
}

// round 9
// speedup vs baseline: 1.9262x; 1.2405x over previous
#include <cuda_runtime.h>
#include <cuda_bf16.h>
#include <cstdint>

#define B 8
#define S 1024
#define DIM 768
#define H 8
#define NEGV -1e10f
#define RS96 0.1020620726159658f  // 1/sqrt(96)
#define NI (B * S)                // 8192 total rows

// ---------------------------------------------------------------------------
// Scratch (static device globals — allocation-free per harness rules)
// ---------------------------------------------------------------------------
__device__ float g_Qt[DIM * NI];  // transposed: [j][i], i = b*S+s (RS96 applied)
__device__ float g_Kt[DIM * NI];
__device__ float g_logit[NI];
__device__ float g_aw[NI];
__device__ float g_R[NI * H];
__device__ float g_T[B * H * DIM];
// bf16 hi/lo splits of inputs
__device__ __nv_bfloat16 g_Xhi[NI * DIM];
__device__ __nv_bfloat16 g_Xlo[NI * DIM];
__device__ __nv_bfloat16 g_Wqhi[DIM * DIM];
__device__ __nv_bfloat16 g_Wqlo[DIM * DIM];
__device__ __nv_bfloat16 g_Wkhi[DIM * DIM];
__device__ __nv_bfloat16 g_Wklo[DIM * DIM];

// ---------------------------------------------------------------------------
#define MMA16816(d, a0, a1, a2, a3, b0, b1)                                    \
    asm volatile("mma.sync.aligned.m16n8k16.row.col.f32.bf16.bf16.f32 "        \
                 "{%0,%1,%2,%3}, {%4,%5,%6,%7}, {%8,%9}, {%0,%1,%2,%3};"       \
                 : "+f"((d)[0]), "+f"((d)[1]), "+f"((d)[2]), "+f"((d)[3])      \
                 : "r"(a0), "r"(a1), "r"(a2), "r"(a3), "r"(b0), "r"(b1))

// ---------------------------------------------------------------------------
__global__ void k0_zeroR() {
    int i = blockIdx.x * blockDim.x + threadIdx.x;
    if (i < NI * H) g_R[i] = 0.f;
}

// ---------------------------------------------------------------------------
// Ksplit: fp32 -> bf16 hi + bf16 lo.
// NOTE: destination picked INSIDE device code — __device__ symbols must
// never be passed as host-side kernel arguments (on GB300/ATS the bogus
// host-shadow address is silently dereferenceable: writes vanish into host
// memory, device globals stay zero).
// ---------------------------------------------------------------------------
__global__ void ksplit_sel(const float* __restrict__ src, int which, int n4) {
    __nv_bfloat16 *hi, *lo;
    if (which == 0)      { hi = g_Xhi;  lo = g_Xlo;  }
    else if (which == 1) { hi = g_Wqhi; lo = g_Wqlo; }
    else                 { hi = g_Wkhi; lo = g_Wklo; }
    int i = blockIdx.x * blockDim.x + threadIdx.x;
    if (i >= n4) return;
    float4 v = ((const float4*)src)[i];
    __nv_bfloat16 h0 = __float2bfloat16(v.x), h1 = __float2bfloat16(v.y);
    __nv_bfloat16 h2 = __float2bfloat16(v.z), h3 = __float2bfloat16(v.w);
    __nv_bfloat16 l0 = __float2bfloat16(v.x - __bfloat162float(h0));
    __nv_bfloat16 l1 = __float2bfloat16(v.y - __bfloat162float(h1));
    __nv_bfloat16 l2 = __float2bfloat16(v.z - __bfloat162float(h2));
    __nv_bfloat16 l3 = __float2bfloat16(v.w - __bfloat162float(h3));
    ((__nv_bfloat162*)hi)[2 * i] = __nv_bfloat162(h0, h1);
    ((__nv_bfloat162*)hi)[2 * i + 1] = __nv_bfloat162(h2, h3);
    ((__nv_bfloat162*)lo)[2 * i] = __nv_bfloat162(l0, l1);
    ((__nv_bfloat162*)lo)[2 * i + 1] = __nv_bfloat162(l2, l3);
}

// ---------------------------------------------------------------------------
// K1a: span logits  l[i] = X[i,:] . w  (masked with NEG where tag==0)
// ---------------------------------------------------------------------------
__global__ void k1a_logits(const float* __restrict__ X,
                           const int* __restrict__ tags,
                           const float* __restrict__ w) {
    int warp = threadIdx.x >> 5, lane = threadIdx.x & 31;
    int row = blockIdx.x * 8 + warp;
    const float4* xr = (const float4*)(X + (size_t)row * DIM);
    const float4* wr = (const float4*)w;
    float s = 0.f;
#pragma unroll
    for (int i = 0; i < 6; i++) {
        float4 a = xr[lane + 32 * i];
        float4 b = wr[lane + 32 * i];
        s += a.x * b.x + a.y * b.y + a.z * b.z + a.w * b.w;
    }
#pragma unroll
    for (int o = 16; o; o >>= 1) s += __shfl_xor_sync(0xffffffffu, s, o);
    if (lane == 0) g_logit[row] = (tags[row] == 0) ? NEGV : s;
}

// ---------------------------------------------------------------------------
__global__ void k1b_softmax() {
    __shared__ float red[256];
    int b = blockIdx.x, t = threadIdx.x;
    float l[4];
#pragma unroll
    for (int i = 0; i < 4; i++) l[i] = g_logit[b * S + t + 256 * i];
    float mx = fmaxf(fmaxf(l[0], l[1]), fmaxf(l[2], l[3]));
    red[t] = mx;
    __syncthreads();
    for (int o = 128; o; o >>= 1) {
        if (t < o) red[t] = fmaxf(red[t], red[t + o]);
        __syncthreads();
    }
    mx = red[0];
    __syncthreads();
    float e[4], sum = 0.f;
#pragma unroll
    for (int i = 0; i < 4; i++) { e[i] = __expf(l[i] - mx); sum += e[i]; }
    red[t] = sum;
    __syncthreads();
    for (int o = 128; o; o >>= 1) {
        if (t < o) red[t] += red[t + o];
        __syncthreads();
    }
    float inv = 1.f / red[0];
#pragma unroll
    for (int i = 0; i < 4; i++) g_aw[b * S + t + 256 * i] = e[i] * inv;
}

// ---------------------------------------------------------------------------
// K2 (mma.sync bf16x3, direct-LDS fragments): Qt = RS96 * X Wq^T,
// Kt = X Wk^T (float, transposed [j][i]).
// CTA 128(i) x 64(j), 8 warps (4x2), warp 32x32 dual (Q,K).
// ---------------------------------------------------------------------------
__global__ void __launch_bounds__(256, 2) k2_mma() {
    __shared__ __align__(16) __nv_bfloat16 As[128 * 40];
    __shared__ __align__(16) __nv_bfloat16 Bq[64 * 40];
    __shared__ __align__(16) __nv_bfloat16 Bk[64 * 40];
    int t = threadIdx.x, l = t & 31, wid = t >> 5;
    int wm = wid & 3, wn = wid >> 2;
    int i0 = blockIdx.x * 128, j0 = blockIdx.y * 64;
    int lg = l >> 2;         // groupID 0..7
    int lk2 = 2 * (l & 3);   // k-pair base 0,2,4,6

    float qacc[2][4][4], kacc[2][4][4];  // [am][n-block(8)][reg]
#pragma unroll
    for (int am = 0; am < 2; am++)
#pragma unroll
        for (int bn = 0; bn < 4; bn++)
#pragma unroll
            for (int r = 0; r < 4; r++) { qacc[am][bn][r] = 0.f; kacc[am][bn][r] = 0.f; }

    for (int term = 0; term < 3; term++) {
        const __nv_bfloat16* XA = (term == 1) ? g_Xlo : g_Xhi;
        const __nv_bfloat16* WQ = (term == 2) ? g_Wqlo : g_Wqhi;
        const __nv_bfloat16* WK = (term == 2) ? g_Wklo : g_Wkhi;
        for (int kb = 0; kb < DIM; kb += 32) {
            int ar = t >> 2, ac = (t & 3) * 8;
            uint4 ra0 = *(const uint4*)(XA + (size_t)(i0 + ar) * DIM + kb + ac);
            uint4 ra1 = *(const uint4*)(XA + (size_t)(i0 + ar + 64) * DIM + kb + ac);
            uint4 rq = *(const uint4*)(WQ + (size_t)(j0 + ar) * DIM + kb + ac);
            uint4 rk = *(const uint4*)(WK + (size_t)(j0 + ar) * DIM + kb + ac);
            __syncthreads();
            *(uint4*)(As + ar * 40 + ac) = ra0;
            *(uint4*)(As + (ar + 64) * 40 + ac) = ra1;
            *(uint4*)(Bq + ar * 40 + ac) = rq;
            *(uint4*)(Bk + ar * 40 + ac) = rk;
            __syncthreads();
#pragma unroll
            for (int kk = 0; kk < 2; kk++) {
                int ko = kk * 16;
                // A fragments: a0=(g,k) a1=(g+8,k) a2=(g,k+8) a3=(g+8,k+8)
                uint32_t a[2][4];
#pragma unroll
                for (int am = 0; am < 2; am++) {
                    const __nv_bfloat16* ap =
                        As + (wm * 32 + am * 16 + lg) * 40 + ko + lk2;
                    a[am][0] = *(const uint32_t*)(ap);
                    a[am][1] = *(const uint32_t*)(ap + 8 * 40);
                    a[am][2] = *(const uint32_t*)(ap + 8);
                    a[am][3] = *(const uint32_t*)(ap + 8 * 40 + 8);
                }
#pragma unroll
                for (int bp = 0; bp < 2; bp++)
#pragma unroll
                    for (int o = 0; o < 2; o++) {
                        int nr = wn * 32 + bp * 16 + o * 8 + lg;
                        // B fragments: b0=(n=g, k) b1=(n=g, k+8)
                        const __nv_bfloat16* bqp = Bq + nr * 40 + ko + lk2;
                        uint32_t q0 = *(const uint32_t*)(bqp);
                        uint32_t q1 = *(const uint32_t*)(bqp + 8);
                        MMA16816(qacc[0][2 * bp + o], a[0][0], a[0][1], a[0][2], a[0][3], q0, q1);
                        MMA16816(qacc[1][2 * bp + o], a[1][0], a[1][1], a[1][2], a[1][3], q0, q1);
                        const __nv_bfloat16* bkp = Bk + nr * 40 + ko + lk2;
                        uint32_t k0 = *(const uint32_t*)(bkp);
                        uint32_t k1 = *(const uint32_t*)(bkp + 8);
                        MMA16816(kacc[0][2 * bp + o], a[0][0], a[0][1], a[0][2], a[0][3], k0, k1);
                        MMA16816(kacc[1][2 * bp + o], a[1][0], a[1][1], a[1][2], a[1][3], k0, k1);
                    }
            }
        }
    }

    // Epilogue: write directly from fragments (c0=(g,2c) c1=(g,2c+1)
    // c2=(g+8,2c) c3=(g+8,2c+1)); transposed [j][i] layout, 8-lane coalesced.
#pragma unroll
    for (int am = 0; am < 2; am++)
#pragma unroll
        for (int bn = 0; bn < 4; bn++) {
            int r = wm * 32 + am * 16 + lg;   // i-local
            int c = wn * 32 + bn * 8 + lk2;   // j-local
            size_t o0 = (size_t)(j0 + c) * NI + i0 + r;
            size_t o1 = (size_t)(j0 + c + 1) * NI + i0 + r;
            g_Qt[o0] = qacc[am][bn][0] * RS96;
            g_Qt[o1] = qacc[am][bn][1] * RS96;
            g_Qt[o0 + 8] = qacc[am][bn][2] * RS96;
            g_Qt[o1 + 8] = qacc[am][bn][3] * RS96;
            g_Kt[o0] = kacc[am][bn][0];
            g_Kt[o1] = kacc[am][bn][1];
            g_Kt[o0 + 8] = kacc[am][bn][2];
            g_Kt[o1 + 8] = kacc[am][bn][3];
        }
}

// ---------------------------------------------------------------------------
// K3: grouped QK^T + heads-softmax + aw-weighted q-reduction (SIMT, proven).
// ---------------------------------------------------------------------------
__global__ void __launch_bounds__(512, 1) k3_attn() {
    __shared__ float Qs[64][68];
    __shared__ float Ks[64][68];
    __shared__ float Rs[64][8];
    int b = blockIdx.z;
    int q0 = blockIdx.y * 64, k0 = blockIdx.x * 64;
    int t = threadIdx.x;
    int h = t & 7, g = t >> 3, gx = g & 7, gy = g >> 3;
    int iq = b * S + q0, ik = b * S + k0;
    int lr = t >> 4, lc = (t & 15) << 2;
    ((float*)Rs)[t] = 0.f;

    float acc[8][8];
#pragma unroll
    for (int a = 0; a < 8; a++)
#pragma unroll
        for (int c = 0; c < 8; c++) acc[a][c] = 0.f;

    for (int mc = 0; mc < DIM; mc += 64) {
        float4 a0 = *(const float4*)(g_Qt + (size_t)(mc + lr) * NI + iq + lc);
        float4 a1 = *(const float4*)(g_Qt + (size_t)(mc + lr + 32) * NI + iq + lc);
        float4 c0 = *(const float4*)(g_Kt + (size_t)(mc + lr) * NI + ik + lc);
        float4 c1 = *(const float4*)(g_Kt + (size_t)(mc + lr + 32) * NI + ik + lc);
        __syncthreads();
        *(float4*)&Qs[lr][lc] = a0;
        *(float4*)&Qs[lr + 32][lc] = a1;
        *(float4*)&Ks[lr][lc] = c0;
        *(float4*)&Ks[lr + 32][lc] = c1;
        __syncthreads();
#pragma unroll
        for (int u = 0; u < 8; u++) {
            int r = u * 8 + h;
            float4 qa = *(float4*)&Qs[r][gy * 8];
            float4 qb = *(float4*)&Qs[r][gy * 8 + 4];
            float4 ka = *(float4*)&Ks[r][gx * 8];
            float4 kb = *(float4*)&Ks[r][gx * 8 + 4];
            float qv[8] = {qa.x, qa.y, qa.z, qa.w, qb.x, qb.y, qb.z, qb.w};
            float kv[8] = {ka.x, ka.y, ka.z, ka.w, kb.x, kb.y, kb.z, kb.w};
#pragma unroll
            for (int qi = 0; qi < 8; qi++)
#pragma unroll
                for (int ki = 0; ki < 8; ki++)
                    acc[qi][ki] += qv[qi] * kv[ki];
        }
    }

    unsigned mask = 0xFFu << ((t & 31) & 24);
    float rk[8];
#pragma unroll
    for (int ki = 0; ki < 8; ki++) rk[ki] = 0.f;
#pragma unroll
    for (int qi = 0; qi < 8; qi++) {
        float aw = g_aw[iq + gy * 8 + qi];
        if (aw != 0.f) {
#pragma unroll
            for (int ki = 0; ki < 8; ki++) {
                float v = acc[qi][ki];
                float mx = v;
                mx = fmaxf(mx, __shfl_xor_sync(mask, mx, 1));
                mx = fmaxf(mx, __shfl_xor_sync(mask, mx, 2));
                mx = fmaxf(mx, __shfl_xor_sync(mask, mx, 4));
                float e = __expf(v - mx);
                float s = e;
                s += __shfl_xor_sync(mask, s, 1);
                s += __shfl_xor_sync(mask, s, 2);
                s += __shfl_xor_sync(mask, s, 4);
                rk[ki] += aw * __fdividef(e, s);
            }
        }
    }
#pragma unroll
    for (int ki = 0; ki < 8; ki++) atomicAdd(&Rs[gx * 8 + ki][h], rk[ki]);
    __syncthreads();
    atomicAdd(&g_R[(size_t)(ik + (t >> 3)) * H + (t & 7)], Rs[t >> 3][t & 7]);
}

// ---------------------------------------------------------------------------
// K4: T[b,h,m] = sum_k R[b,k,h] * X[b,k,m]
// ---------------------------------------------------------------------------
__global__ void __launch_bounds__(256) k4_T(const float* __restrict__ X) {
    __shared__ float Xs[64][64];
    __shared__ float Rsm[64][8];
    int b = blockIdx.y;
    int m0 = blockIdx.x * 64;
    int t = threadIdx.x;
    int m = t & 63, hh = t >> 6;
    float acc0 = 0.f, acc1 = 0.f;
    for (int kc = 0; kc < S; kc += 64) {
#pragma unroll
        for (int u = 0; u < 4; u++) {
            int lin = t + 256 * u;
            int r = lin >> 4, c = (lin & 15) << 2;
            *(float4*)&Xs[r][c] =
                *(const float4*)(X + (size_t)(b * S + kc + r) * DIM + m0 + c);
        }
        {
            float2 v = *(const float2*)(g_R + ((size_t)b * S + kc) * H + t * 2);
            *(float2*)&((float*)Rsm)[t * 2] = v;
        }
        __syncthreads();
#pragma unroll 8
        for (int k = 0; k < 64; k++) {
            float x = Xs[k][m];
            acc0 += Rsm[k][hh] * x;
            acc1 += Rsm[k][hh + 4] * x;
        }
        __syncthreads();
    }
    g_T[((size_t)b * H + hh) * DIM + m0 + m] = acc0;
    g_T[((size_t)b * H + hh + 4) * DIM + m0 + m] = acc1;
}

// ---------------------------------------------------------------------------
// K5: out[b,j] = sum_m Wv[j,m] * T[b, j&7, m]
// ---------------------------------------------------------------------------
__global__ void k5_out(const float* __restrict__ Wv, float* __restrict__ out) {
    int warp = threadIdx.x >> 5, lane = threadIdx.x & 31;
    int g = blockIdx.x * 8 + warp;
    int b = g / DIM, j = g % DIM;
    int h = j & 7;
    const float4* wr = (const float4*)(Wv + (size_t)j * DIM);
    const float4* tr = (const float4*)(g_T + ((size_t)b * H + h) * DIM);
    float s = 0.f;
#pragma unroll
    for (int i = 0; i < 6; i++) {
        float4 a = wr[lane + 32 * i];
        float4 c = tr[lane + 32 * i];
        s += a.x * c.x + a.y * c.y + a.z * c.z + a.w * c.w;
    }
#pragma unroll
    for (int o = 16; o; o >>= 1) s += __shfl_xor_sync(0xffffffffu, s, o);
    if (lane == 0) out[(size_t)b * DIM + j] = s;
}

// ---------------------------------------------------------------------------
extern "C" void kernel_launch(void* const* d_in, const int* in_sizes, int n_in,
                              void* d_out, int out_size) {
    const float* X    = (const float*)d_in[0];
    const int*   tags = (const int*)d_in[1];
    const float* w    = (const float*)d_in[2];
    const float* Wq   = (const float*)d_in[3];
    const float* Wk   = (const float*)d_in[4];
    const float* Wv   = (const float*)d_in[5];
    float* out = (float*)d_out;

    k0_zeroR<<<(NI * H + 255) / 256, 256>>>();
    ksplit_sel<<<(NI * DIM / 4 + 255) / 256, 256>>>(X, 0, NI * DIM / 4);
    ksplit_sel<<<(DIM * DIM / 4 + 255) / 256, 256>>>(Wq, 1, DIM * DIM / 4);
    ksplit_sel<<<(DIM * DIM / 4 + 255) / 256, 256>>>(Wk, 2, DIM * DIM / 4);
    k1a_logits<<<NI / 8, 256>>>(X, tags, w);
    k1b_softmax<<<B, 256>>>();
    k2_mma<<<dim3(64, 12), 256>>>();
    k3_attn<<<dim3(16, 16, 8), 512>>>();
    k4_T<<<dim3(12, 8), 256>>>(X);
    k5_out<<<768, 256>>>(Wv, out);
}